// round 2
// baseline (speedup 1.0000x reference)
#include <cuda_runtime.h>
#include <math.h>

#define EMB 64
#define RNN 128
#define BB  512
#define LL  256
#define KK  18
#define G   8
#define ZC  512   // 4*RNN

// Scratch (static device allocations; no cudaMalloc allowed)
__device__ float g_Z[2][LL][BB][ZC];        // precomputed x@Wx + b, per direction
__device__ float g_hcat[LL][BB][2 * RNN];   // concat(h_fwd, h_bwd)
__device__ float g_logits[BB][LL][KK];

// ---------------------------------------------------------------------------
// Kernel 1: Z[dir][t][b][:] = E[inputs[b,t]] @ Wx_dir + b_dir   (both dirs)
// grid: (L, B/G), block: 512 threads (one per gate column)
// ---------------------------------------------------------------------------
__global__ __launch_bounds__(512) void zpre_kernel(
    const int* __restrict__ inputs, const float* __restrict__ E,
    const float* __restrict__ Wx_f, const float* __restrict__ b_f,
    const float* __restrict__ Wx_b, const float* __restrict__ b_b)
{
    int t  = blockIdx.x;
    int b0 = blockIdx.y * G;
    __shared__ __align__(16) float x_s[EMB][G];   // [e][row]
    int tid = threadIdx.x;
    {
        int r = tid >> 6;      // 0..7
        int e = tid & 63;      // 0..63
        int tok = inputs[(b0 + r) * LL + t];
        x_s[e][r] = E[tok * EMB + e];
    }
    __syncthreads();

    float accf[G], accb[G];
    float bfv = b_f[tid], bbv = b_b[tid];
#pragma unroll
    for (int g = 0; g < G; g++) { accf[g] = bfv; accb[g] = bbv; }

    const float* wf = Wx_f + tid;
    const float* wb = Wx_b + tid;
#pragma unroll 8
    for (int e = 0; e < EMB; e++) {
        float wfv = wf[e * ZC];
        float wbv = wb[e * ZC];
        float4 x0 = *(const float4*)&x_s[e][0];
        float4 x1 = *(const float4*)&x_s[e][4];
        accf[0] = fmaf(wfv, x0.x, accf[0]);
        accf[1] = fmaf(wfv, x0.y, accf[1]);
        accf[2] = fmaf(wfv, x0.z, accf[2]);
        accf[3] = fmaf(wfv, x0.w, accf[3]);
        accf[4] = fmaf(wfv, x1.x, accf[4]);
        accf[5] = fmaf(wfv, x1.y, accf[5]);
        accf[6] = fmaf(wfv, x1.z, accf[6]);
        accf[7] = fmaf(wfv, x1.w, accf[7]);
        accb[0] = fmaf(wbv, x0.x, accb[0]);
        accb[1] = fmaf(wbv, x0.y, accb[1]);
        accb[2] = fmaf(wbv, x0.z, accb[2]);
        accb[3] = fmaf(wbv, x0.w, accb[3]);
        accb[4] = fmaf(wbv, x1.x, accb[4]);
        accb[5] = fmaf(wbv, x1.y, accb[5]);
        accb[6] = fmaf(wbv, x1.z, accb[6]);
        accb[7] = fmaf(wbv, x1.w, accb[7]);
    }
    float* zf = &g_Z[0][t][b0][0];
    float* zb = &g_Z[1][t][b0][0];
#pragma unroll
    for (int g = 0; g < G; g++) {
        zf[g * ZC + tid] = accf[g];
        zb[g * ZC + tid] = accb[g];
    }
}

// ---------------------------------------------------------------------------
// Kernel 2: persistent LSTM. 128 blocks = 2 dirs x 64 batch-groups (G=8 rows).
// 512 threads; thread j owns gate column j of z. Wh streamed from L2 per step
// (shared by all 64 blocks of a direction -> L2 resident).
// ---------------------------------------------------------------------------
__global__ __launch_bounds__(512) void lstm_kernel(
    const float* __restrict__ Wh_f, const float* __restrict__ Wh_b)
{
    int dir = blockIdx.x >> 6;       // 0 fwd, 1 bwd
    int bi  = blockIdx.x & 63;
    int b0  = bi * G;
    const float* __restrict__ Wh = dir ? Wh_b : Wh_f;

    __shared__ __align__(16) float h_s[RNN][G];      // [k][row], float4-friendly
    __shared__ float c_s[G][RNN];
    __shared__ float act_s[4][G][RNN];               // i,f,g,o activations

    int tid  = threadIdx.x;
    int gate = tid >> 7;     // 0..3
    int unit = tid & 127;

    for (int i = tid; i < RNN * G; i += 512) h_s[i >> 3][i & 7] = 0.0f;
    for (int i = tid; i < G * RNN; i += 512) c_s[i >> 7][i & 127] = 0.0f;
    __syncthreads();

    const float* whc = Wh + tid;

    for (int step = 0; step < LL; step++) {
        int t = dir ? (LL - 1 - step) : step;

        float acc[G];
        const float* zp = &g_Z[dir][t][b0][0];
#pragma unroll
        for (int g = 0; g < G; g++) acc[g] = zp[g * ZC + tid];

#pragma unroll 4
        for (int k = 0; k < RNN; k++) {
            float w = whc[k * ZC];
            float4 h0 = *(const float4*)&h_s[k][0];
            float4 h1 = *(const float4*)&h_s[k][4];
            acc[0] = fmaf(w, h0.x, acc[0]);
            acc[1] = fmaf(w, h0.y, acc[1]);
            acc[2] = fmaf(w, h0.z, acc[2]);
            acc[3] = fmaf(w, h0.w, acc[3]);
            acc[4] = fmaf(w, h1.x, acc[4]);
            acc[5] = fmaf(w, h1.y, acc[5]);
            acc[6] = fmaf(w, h1.z, acc[6]);
            acc[7] = fmaf(w, h1.w, acc[7]);
        }

        // activations: gates 0,1,3 -> sigmoid; gate 2 -> tanh
#pragma unroll
        for (int g = 0; g < G; g++) {
            float z = acc[g];
            float a = (gate == 2) ? tanhf(z) : (1.0f / (1.0f + expf(-z)));
            act_s[gate][g][unit] = a;
        }
        __syncthreads();   // act_s ready; h_s free to overwrite

        // c/h update: 1024 cells over 512 threads (2 each)
#pragma unroll
        for (int rep = 0; rep < 2; rep++) {
            int idx = tid + rep * 512;
            int g = idx >> 7, u = idx & 127;
            float iv = act_s[0][g][u];
            float fv = act_s[1][g][u];
            float gv = act_s[2][g][u];
            float ov = act_s[3][g][u];
            float c = fv * c_s[g][u] + iv * gv;
            c_s[g][u] = c;
            float h = ov * tanhf(c);
            h_s[u][g] = h;
            g_hcat[t][b0 + g][dir * RNN + u] = h;
        }
        __syncthreads();   // h_s ready for next step
    }
}

// ---------------------------------------------------------------------------
// Kernel 3: logits[b][t][k] = hcat[t][b][:] . Wd[:,k] + bd[k]
// one warp per (b,t) row; lanes 0..17 hold output classes
// ---------------------------------------------------------------------------
__global__ __launch_bounds__(256) void logits_kernel(
    const float* __restrict__ Wd, const float* __restrict__ bd)
{
    __shared__ float Wd_s[2 * RNN * KK];
    __shared__ float bd_s[KK];
    int tid = threadIdx.x;
    for (int i = tid; i < 2 * RNN * KK; i += 256) Wd_s[i] = Wd[i];
    if (tid < KK) bd_s[tid] = bd[tid];
    __syncthreads();

    int warp = (blockIdx.x * 256 + tid) >> 5;
    int lane = tid & 31;
    if (warp >= BB * LL) return;
    int b = warp >> 8;       // / L
    int t = warp & 255;

    const float* hrow = &g_hcat[t][b][0];
    int k = (lane < KK) ? lane : 0;
    float acc = bd_s[k];
    for (int e0 = 0; e0 < 2 * RNN; e0 += 32) {
        float hv = hrow[e0 + lane];
#pragma unroll
        for (int i = 0; i < 32; i++) {
            float h = __shfl_sync(0xffffffffu, hv, i);
            acc = fmaf(h, Wd_s[(e0 + i) * KK + k], acc);
        }
    }
    if (lane < KK) g_logits[b][t][k] = acc;
}

// ---------------------------------------------------------------------------
// Kernel 4: CRF log-likelihood. One warp per batch row; lanes 0..17 = classes.
// grid 128 x 128 threads (4 warps/block)
// ---------------------------------------------------------------------------
__global__ __launch_bounds__(128) void crf_kernel(
    const int* __restrict__ labels, const float* __restrict__ T,
    float* __restrict__ out, int out_size)
{
    __shared__ float T_s[KK * KK];
    int tid = threadIdx.x;
    for (int i = tid; i < KK * KK; i += 128) T_s[i] = T[i];
    __syncthreads();

    int warp = tid >> 5;
    int lane = tid & 31;
    int b = blockIdx.x * 4 + warp;
    if (b >= BB) return;

    const int* lab = labels + b * LL;

    // lengths[b] = count(labels != 0)
    int cnt = 0;
    for (int l = lane; l < LL; l += 32) cnt += (lab[l] != 0);
#pragma unroll
    for (int off = 16; off; off >>= 1) cnt += __shfl_xor_sync(0xffffffffu, cnt, off);
    int len = cnt;

    // unary + binary scores
    float us = 0.0f, bs = 0.0f;
    for (int l = lane; l < LL; l += 32) {
        int y = lab[l];
        if (l < len) us += g_logits[b][l][y];
        if (l >= 1 && l < len) bs += T_s[lab[l - 1] * KK + y];
    }
#pragma unroll
    for (int off = 16; off; off >>= 1) {
        us += __shfl_xor_sync(0xffffffffu, us, off);
        bs += __shfl_xor_sync(0xffffffffu, bs, off);
    }

    // forward algorithm
    int k = (lane < KK) ? lane : 0;
    float alpha = (lane < KK) ? g_logits[b][0][k] : -1e30f;
    for (int l = 1; l < LL; l++) {
        float v[KK];
        float vmax = -1e30f;
#pragma unroll
        for (int k1 = 0; k1 < KK; k1++) {
            float ak = __shfl_sync(0xffffffffu, alpha, k1);
            v[k1] = ak + T_s[k1 * KK + k];
            vmax = fmaxf(vmax, v[k1]);
        }
        float s = 0.0f;
#pragma unroll
        for (int k1 = 0; k1 < KK; k1++) s += expf(v[k1] - vmax);
        float na = vmax + logf(s) + g_logits[b][l][k];
        if (lane < KK && l < len) alpha = na;
    }

    // log_norm = logsumexp(alpha)
    float m = alpha;
#pragma unroll
    for (int off = 16; off; off >>= 1) m = fmaxf(m, __shfl_xor_sync(0xffffffffu, m, off));
    float es = (lane < KK) ? expf(alpha - m) : 0.0f;
#pragma unroll
    for (int off = 16; off; off >>= 1) es += __shfl_xor_sync(0xffffffffu, es, off);
    float lse = m + logf(es);

    if (lane == 0 && b < out_size) out[b] = us + bs - lse;
}

// ---------------------------------------------------------------------------
// Kernel 5: copy T (second output of the reference tuple)
// ---------------------------------------------------------------------------
__global__ void copy_T_kernel(const float* __restrict__ T, float* __restrict__ out,
                              int out_size)
{
    int i = blockIdx.x * blockDim.x + threadIdx.x;
    if (i < KK * KK && (BB + i) < out_size) out[BB + i] = T[i];
}

// ---------------------------------------------------------------------------
extern "C" void kernel_launch(void* const* d_in, const int* in_sizes, int n_in,
                              void* d_out, int out_size)
{
    const int*   inputs = (const int*)  d_in[0];
    const int*   labels = (const int*)  d_in[1];
    const float* E      = (const float*)d_in[2];
    const float* Wx_f   = (const float*)d_in[3];
    const float* Wh_f   = (const float*)d_in[4];
    const float* b_f    = (const float*)d_in[5];
    const float* Wx_b   = (const float*)d_in[6];
    const float* Wh_b   = (const float*)d_in[7];
    const float* b_b    = (const float*)d_in[8];
    const float* Wd     = (const float*)d_in[9];
    const float* bd     = (const float*)d_in[10];
    const float* T      = (const float*)d_in[11];
    float* out = (float*)d_out;

    dim3 zg(LL, BB / G);
    zpre_kernel<<<zg, 512>>>(inputs, E, Wx_f, b_f, Wx_b, b_b);
    lstm_kernel<<<128, 512>>>(Wh_f, Wh_b);
    logits_kernel<<<(BB * LL * 32) / 256, 256>>>(Wd, bd);
    crf_kernel<<<BB / 4, 128>>>(labels, T, out, out_size);
    copy_T_kernel<<<2, 256>>>(T, out, out_size);
}

// round 3
// speedup vs baseline: 1.5960x; 1.5960x over previous
#include <cuda_runtime.h>
#include <math.h>

#define EMB 64
#define RNN 128
#define BB  512
#define LL  256
#define KK  18
#define G   8
#define ZC  512   // 4*RNN
#define VOCAB 30001
#define K1  96    // Wh rows cached in smem
#define K2  32    // Wh rows cached in registers (RNN - K1)
#define PG  32    // vocab rows per pbuild block
#define LR  28    // (b,t) rows per logits block

// Scratch (static device allocations; no cudaMalloc allowed)
__device__ float g_P[2][VOCAB][ZC];        // E@Wx + b per dir (~123 MB, ~L2-resident)
__device__ float g_hcat[LL][BB][2 * RNN];  // concat(h_fwd, h_bwd)
__device__ float g_logits[BB][LL][KK];

typedef unsigned long long u64;

__device__ __forceinline__ u64 pk2(float lo, float hi) {
    u64 r; asm("mov.b64 %0,{%1,%2};" : "=l"(r) : "f"(lo), "f"(hi)); return r;
}
__device__ __forceinline__ void upk2(u64 v, float& lo, float& hi) {
    asm("mov.b64 {%0,%1},%2;" : "=f"(lo), "=f"(hi) : "l"(v));
}
__device__ __forceinline__ void ffma2(u64& d, u64 a, u64 b) {
    asm("fma.rn.f32x2 %0,%1,%2,%0;" : "+l"(d) : "l"(a), "l"(b));
}

// ---------------------------------------------------------------------------
// Kernel 1: P[dir][v][:] = E[v] @ Wx_dir + b_dir  (vocab-level factoring)
// grid: (ceil(VOCAB/PG), 2), 512 threads (one per gate column)
// ---------------------------------------------------------------------------
__global__ __launch_bounds__(512) void pbuild_kernel(
    const float* __restrict__ E,
    const float* __restrict__ Wx_f, const float* __restrict__ b_f,
    const float* __restrict__ Wx_b, const float* __restrict__ b_b)
{
    int dir = blockIdx.y;
    int r0  = blockIdx.x * PG;
    const float* __restrict__ Wx = dir ? Wx_b : Wx_f;
    const float* __restrict__ bs = dir ? b_b : b_f;

    __shared__ __align__(16) float x_s[EMB][PG];
    int tid = threadIdx.x;
    for (int i = tid; i < PG * EMB; i += 512) {
        int r = i >> 6, e = i & 63;
        int row = r0 + r;
        x_s[e][r] = (row < VOCAB) ? E[row * EMB + e] : 0.0f;
    }
    __syncthreads();

    float bv = bs[tid];
    u64 bp = pk2(bv, bv);
    u64 acc[PG / 2];
#pragma unroll
    for (int p = 0; p < PG / 2; p++) acc[p] = bp;

    const float* wc = Wx + tid;
#pragma unroll 4
    for (int e = 0; e < EMB; e++) {
        float w = wc[e * ZC];
        u64 wd = pk2(w, w);
        const u64* xp = (const u64*)&x_s[e][0];
#pragma unroll
        for (int p = 0; p < PG / 2; p++) ffma2(acc[p], wd, xp[p]);
    }

#pragma unroll
    for (int p = 0; p < PG / 2; p++) {
        float lo, hi; upk2(acc[p], lo, hi);
        int ra = r0 + 2 * p, rb = ra + 1;
        if (ra < VOCAB) g_P[dir][ra][tid] = lo;
        if (rb < VOCAB) g_P[dir][rb][tid] = hi;
    }
}

// ---------------------------------------------------------------------------
// Kernel 2: persistent LSTM. 128 blocks = 2 dirs x 64 batch-groups (G=8 rows).
// Wh fully on-chip: 96 rows in smem (192KB), 32 rows in regs. Z replaced by a
// register-prefetched gather from g_P (tokens known one step ahead).
// ---------------------------------------------------------------------------
__global__ __launch_bounds__(512, 1) void lstm_kernel(
    const int* __restrict__ inputs,
    const float* __restrict__ Wh_f, const float* __restrict__ Wh_b)
{
    extern __shared__ char lsm[];
    float* Wh_s = (float*)lsm;                                        // K1*ZC floats
    float (*h_s)[G]        = (float(*)[G])       (lsm + K1 * ZC * 4);                  // [RNN][G]
    float (*act_s)[G][RNN] = (float(*)[G][RNN])  (lsm + K1 * ZC * 4 + RNN * G * 4);    // [4][G][RNN]
    int   (*tok_s)[LL]     = (int(*)[LL])        (lsm + K1 * ZC * 4 + RNN * G * 4 + 4 * G * RNN * 4);

    int dir = blockIdx.x >> 6;
    int bi  = blockIdx.x & 63;
    int b0  = bi * G;
    const float* __restrict__ Wh = dir ? Wh_b : Wh_f;
    int tid = threadIdx.x;

    // load Wh: 96 rows -> smem, 32 rows -> registers (this thread's column)
    for (int i = tid; i < K1 * ZC; i += 512) Wh_s[i] = Wh[i];
    float wreg[K2];
#pragma unroll
    for (int i = 0; i < K2; i++) wreg[i] = Wh[(K1 + i) * ZC + tid];

    // tokens for this batch group
    for (int i = tid; i < G * LL; i += 512) {
        int g = i >> 8, t = i & 255;
        tok_s[g][t] = inputs[(b0 + g) * LL + t];
    }
    for (int i = tid; i < RNN * G; i += 512) ((float*)h_s)[i] = 0.0f;
    __syncthreads();

    int gate = tid >> 7, unit = tid & 127;
    float c0 = 0.0f, c1 = 0.0f;

    int t0 = dir ? (LL - 1) : 0;
    float pf[G];
#pragma unroll
    for (int g = 0; g < G; g++) pf[g] = g_P[dir][tok_s[g][t0]][tid];

    for (int step = 0; step < LL; step++) {
        int t = dir ? (LL - 1 - step) : step;

        u64 acc[G / 2];
#pragma unroll
        for (int p = 0; p < G / 2; p++) acc[p] = pk2(pf[2 * p], pf[2 * p + 1]);

        // prefetch next step's P rows (latency hidden behind the k loop)
        int tn = (step + 1 < LL) ? (dir ? t - 1 : t + 1) : t;
#pragma unroll
        for (int g = 0; g < G; g++) pf[g] = g_P[dir][tok_s[g][tn]][tid];

        const float* ws = Wh_s + tid;
#pragma unroll 4
        for (int k = 0; k < K1; k++) {
            float w = ws[k * ZC];
            u64 wd = pk2(w, w);
            const u64* hp = (const u64*)&h_s[k][0];
            ffma2(acc[0], wd, hp[0]);
            ffma2(acc[1], wd, hp[1]);
            ffma2(acc[2], wd, hp[2]);
            ffma2(acc[3], wd, hp[3]);
        }
#pragma unroll
        for (int i = 0; i < K2; i++) {
            u64 wd = pk2(wreg[i], wreg[i]);
            const u64* hp = (const u64*)&h_s[K1 + i][0];
            ffma2(acc[0], wd, hp[0]);
            ffma2(acc[1], wd, hp[1]);
            ffma2(acc[2], wd, hp[2]);
            ffma2(acc[3], wd, hp[3]);
        }

        // activations: gates 0,1,3 -> sigmoid; gate 2 -> tanh
#pragma unroll
        for (int p = 0; p < G / 2; p++) {
            float zlo, zhi; upk2(acc[p], zlo, zhi);
            float a0 = (gate == 2) ? tanhf(zlo) : (1.0f / (1.0f + expf(-zlo)));
            float a1 = (gate == 2) ? tanhf(zhi) : (1.0f / (1.0f + expf(-zhi)));
            act_s[gate][2 * p][unit]     = a0;
            act_s[gate][2 * p + 1][unit] = a1;
        }
        __syncthreads();

        // c/h update: 1024 cells, 2 per thread; c lives in registers
        {
            int g = tid >> 7, u = tid & 127;
            float iv = act_s[0][g][u], fv = act_s[1][g][u];
            float gv = act_s[2][g][u], ov = act_s[3][g][u];
            c0 = fv * c0 + iv * gv;
            float h = ov * tanhf(c0);
            h_s[u][g] = h;
            g_hcat[t][b0 + g][dir * RNN + u] = h;

            int idx = tid + 512; int g2 = idx >> 7, u2 = idx & 127;
            float iv2 = act_s[0][g2][u2], fv2 = act_s[1][g2][u2];
            float gv2 = act_s[2][g2][u2], ov2 = act_s[3][g2][u2];
            c1 = fv2 * c1 + iv2 * gv2;
            float h2 = ov2 * tanhf(c1);
            h_s[u2][g2] = h2;
            g_hcat[t][b0 + g2][dir * RNN + u2] = h2;
        }
        __syncthreads();
    }
}

// ---------------------------------------------------------------------------
// Kernel 3: logits[b][t][k] = hcat[bt] . Wd[:,k] + bd[k]
// smem-tiled: LR rows + transposed/packed Wd; thread = (row, class), FFMA2
// ---------------------------------------------------------------------------
__global__ __launch_bounds__(512) void logits_kernel(
    const float* __restrict__ Wd, const float* __restrict__ bd)
{
    __shared__ __align__(16) float h_s[LR][2 * RNN];
    __shared__ __align__(16) float2 Wt2[KK][RNN + 1];   // [k][e-pair], padded
    __shared__ float bd_s[KK];

    int tid = threadIdx.x;
    int bt0 = blockIdx.x * LR;

    for (int i = tid; i < KK * RNN; i += 512) {
        int k = i / RNN, e2 = i % RNN;
        Wt2[k][e2] = make_float2(Wd[(2 * e2) * KK + k], Wd[(2 * e2 + 1) * KK + k]);
    }
    if (tid < KK) bd_s[tid] = bd[tid];
    for (int i = tid; i < LR * 2 * RNN; i += 512) {
        int r = i >> 8, e = i & 255;
        int bt = bt0 + r;
        if (bt < BB * LL) {
            int b = bt >> 8, t = bt & 255;
            h_s[r][e] = g_hcat[t][b][e];
        }
    }
    __syncthreads();

    if (tid >= LR * KK) return;
    int r = tid / KK, k = tid % KK;
    int bt = bt0 + r;
    if (bt >= BB * LL) return;

    u64 acc = 0;
    const u64* hp = (const u64*)&h_s[r][0];
    const u64* wp = (const u64*)&Wt2[k][0];
#pragma unroll 8
    for (int e2 = 0; e2 < RNN; e2++) ffma2(acc, hp[e2], wp[e2]);

    float lo, hi; upk2(acc, lo, hi);
    int b = bt >> 8, t = bt & 255;
    g_logits[b][t][k] = lo + hi + bd_s[k];
}

// ---------------------------------------------------------------------------
// Kernel 4: CRF log-likelihood. One warp per batch row; lanes 0..17 = classes.
// ---------------------------------------------------------------------------
__global__ __launch_bounds__(128) void crf_kernel(
    const int* __restrict__ labels, const float* __restrict__ T,
    float* __restrict__ out, int out_size)
{
    __shared__ float T_s[KK * KK];
    int tid = threadIdx.x;
    for (int i = tid; i < KK * KK; i += 128) T_s[i] = T[i];
    __syncthreads();

    int warp = tid >> 5;
    int lane = tid & 31;
    int b = blockIdx.x * 4 + warp;
    if (b >= BB) return;

    const int* lab = labels + b * LL;

    int cnt = 0;
    for (int l = lane; l < LL; l += 32) cnt += (lab[l] != 0);
#pragma unroll
    for (int off = 16; off; off >>= 1) cnt += __shfl_xor_sync(0xffffffffu, cnt, off);
    int len = cnt;

    float us = 0.0f, bs = 0.0f;
    for (int l = lane; l < LL; l += 32) {
        int y = lab[l];
        if (l < len) us += g_logits[b][l][y];
        if (l >= 1 && l < len) bs += T_s[lab[l - 1] * KK + y];
    }
#pragma unroll
    for (int off = 16; off; off >>= 1) {
        us += __shfl_xor_sync(0xffffffffu, us, off);
        bs += __shfl_xor_sync(0xffffffffu, bs, off);
    }

    int k = (lane < KK) ? lane : 0;
    float alpha = (lane < KK) ? g_logits[b][0][k] : -1e30f;
    for (int l = 1; l < LL; l++) {
        float v[KK];
        float vmax = -1e30f;
#pragma unroll
        for (int k1 = 0; k1 < KK; k1++) {
            float ak = __shfl_sync(0xffffffffu, alpha, k1);
            v[k1] = ak + T_s[k1 * KK + k];
            vmax = fmaxf(vmax, v[k1]);
        }
        float s = 0.0f;
#pragma unroll
        for (int k1 = 0; k1 < KK; k1++) s += expf(v[k1] - vmax);
        float na = vmax + logf(s) + g_logits[b][l][k];
        if (lane < KK && l < len) alpha = na;
    }

    float m = alpha;
#pragma unroll
    for (int off = 16; off; off >>= 1) m = fmaxf(m, __shfl_xor_sync(0xffffffffu, m, off));
    float es = (lane < KK) ? expf(alpha - m) : 0.0f;
#pragma unroll
    for (int off = 16; off; off >>= 1) es += __shfl_xor_sync(0xffffffffu, es, off);
    float lse = m + logf(es);

    if (lane == 0 && b < out_size) out[b] = us + bs - lse;
}

// ---------------------------------------------------------------------------
// Kernel 5: copy T (second output of the reference tuple)
// ---------------------------------------------------------------------------
__global__ void copy_T_kernel(const float* __restrict__ T, float* __restrict__ out,
                              int out_size)
{
    int i = blockIdx.x * blockDim.x + threadIdx.x;
    if (i < KK * KK && (BB + i) < out_size) out[BB + i] = T[i];
}

// ---------------------------------------------------------------------------
extern "C" void kernel_launch(void* const* d_in, const int* in_sizes, int n_in,
                              void* d_out, int out_size)
{
    const int*   inputs = (const int*)  d_in[0];
    const int*   labels = (const int*)  d_in[1];
    const float* E      = (const float*)d_in[2];
    const float* Wx_f   = (const float*)d_in[3];
    const float* Wh_f   = (const float*)d_in[4];
    const float* b_f    = (const float*)d_in[5];
    const float* Wx_b   = (const float*)d_in[6];
    const float* Wh_b   = (const float*)d_in[7];
    const float* b_b    = (const float*)d_in[8];
    const float* Wd     = (const float*)d_in[9];
    const float* bd     = (const float*)d_in[10];
    const float* T      = (const float*)d_in[11];
    float* out = (float*)d_out;

    const int lstm_smem = K1 * ZC * 4 + RNN * G * 4 + 4 * G * RNN * 4 + G * LL * 4;
    cudaFuncSetAttribute(lstm_kernel, cudaFuncAttributeMaxDynamicSharedMemorySize, lstm_smem);

    dim3 pg((VOCAB + PG - 1) / PG, 2);
    pbuild_kernel<<<pg, 512>>>(E, Wx_f, b_f, Wx_b, b_b);
    lstm_kernel<<<128, 512, lstm_smem>>>(inputs, Wh_f, Wh_b);
    int nbt = BB * LL;
    logits_kernel<<<(nbt + LR - 1) / LR, 512>>>(Wd, bd);
    crf_kernel<<<BB / 4, 128>>>(labels, T, out, out_size);
    copy_T_kernel<<<2, 256>>>(T, out, out_size);
}

// round 4
// speedup vs baseline: 1.7142x; 1.0741x over previous
#include <cuda_runtime.h>
#include <math.h>

#define EMB 64
#define RNN 128
#define BB  512
#define LL  256
#define KK  18
#define G   8
#define ZC  512   // 4*RNN
#define VOCAB 30001
#define K1  80    // Wh rows cached in smem
#define K2  48    // Wh rows cached in registers (RNN - K1)
#define PG  32    // vocab rows per pbuild block
#define LR  28    // (b,t) rows per logits block

// Scratch (static device allocations; no cudaMalloc allowed)
__device__ float g_P[2][VOCAB][ZC];        // E@Wx + b per dir (~123 MB)
__device__ float g_hcat[LL][BB][2 * RNN];  // concat(h_fwd, h_bwd)
__device__ float g_logits[BB][LL][KK];

typedef unsigned long long u64;

__device__ __forceinline__ u64 pk2(float lo, float hi) {
    u64 r; asm("mov.b64 %0,{%1,%2};" : "=l"(r) : "f"(lo), "f"(hi)); return r;
}
__device__ __forceinline__ void upk2(u64 v, float& lo, float& hi) {
    asm("mov.b64 {%0,%1},%2;" : "=f"(lo), "=f"(hi) : "l"(v));
}
__device__ __forceinline__ void ffma2(u64& d, u64 a, u64 b) {
    asm("fma.rn.f32x2 %0,%1,%2,%0;" : "+l"(d) : "l"(a), "l"(b));
}
__device__ __forceinline__ float fast_tanh(float x) {
    float y; asm("tanh.approx.f32 %0, %1;" : "=f"(y) : "f"(x)); return y;
}
__device__ __forceinline__ float fast_sigmoid(float x) {
    return __fdividef(1.0f, 1.0f + __expf(-x));
}

// ---------------------------------------------------------------------------
// Kernel 1: P[dir][v][:] = E[v] @ Wx_dir + b_dir  (vocab-level factoring)
// ---------------------------------------------------------------------------
__global__ __launch_bounds__(512) void pbuild_kernel(
    const float* __restrict__ E,
    const float* __restrict__ Wx_f, const float* __restrict__ b_f,
    const float* __restrict__ Wx_b, const float* __restrict__ b_b)
{
    int dir = blockIdx.y;
    int r0  = blockIdx.x * PG;
    const float* __restrict__ Wx = dir ? Wx_b : Wx_f;
    const float* __restrict__ bs = dir ? b_b : b_f;

    __shared__ __align__(16) float x_s[EMB][PG];
    int tid = threadIdx.x;
    for (int i = tid; i < PG * EMB; i += 512) {
        int r = i >> 6, e = i & 63;
        int row = r0 + r;
        x_s[e][r] = (row < VOCAB) ? E[row * EMB + e] : 0.0f;
    }
    __syncthreads();

    float bv = bs[tid];
    u64 bp = pk2(bv, bv);
    u64 acc[PG / 2];
#pragma unroll
    for (int p = 0; p < PG / 2; p++) acc[p] = bp;

    const float* wc = Wx + tid;
#pragma unroll 4
    for (int e = 0; e < EMB; e++) {
        float w = wc[e * ZC];
        u64 wd = pk2(w, w);
        const u64* xp = (const u64*)&x_s[e][0];
#pragma unroll
        for (int p = 0; p < PG / 2; p++) ffma2(acc[p], wd, xp[p]);
    }

#pragma unroll
    for (int p = 0; p < PG / 2; p++) {
        float lo, hi; upk2(acc[p], lo, hi);
        int ra = r0 + 2 * p, rb = ra + 1;
        if (ra < VOCAB) g_P[dir][ra][tid] = lo;
        if (rb < VOCAB) g_P[dir][rb][tid] = hi;
    }
}

// ---------------------------------------------------------------------------
// Kernel 2: persistent LSTM. 128 blocks = 2 dirs x 64 batch-groups (G=8 rows).
// Wh on-chip: 80 rows smem + 48 rows regs. h loads as LDS.128. MUFU activations.
// ---------------------------------------------------------------------------
__global__ __launch_bounds__(512, 1) void lstm_kernel(
    const int* __restrict__ inputs,
    const float* __restrict__ Wh_f, const float* __restrict__ Wh_b)
{
    extern __shared__ char lsm[];
    float* Wh_s = (float*)lsm;                                                          // K1*ZC
    float (*h_s)[G]        = (float(*)[G])      (lsm + K1 * ZC * 4);                    // [RNN][G]
    float (*act_s)[G][RNN] = (float(*)[G][RNN]) (lsm + K1 * ZC * 4 + RNN * G * 4);      // [4][G][RNN]
    int   (*tok_s)[LL]     = (int(*)[LL])       (lsm + K1 * ZC * 4 + RNN * G * 4 + 4 * G * RNN * 4);

    int dir = blockIdx.x >> 6;
    int bi  = blockIdx.x & 63;
    int b0  = bi * G;
    const float* __restrict__ Wh = dir ? Wh_b : Wh_f;
    int tid = threadIdx.x;

    for (int i = tid; i < K1 * ZC; i += 512) Wh_s[i] = Wh[i];
    float wreg[K2];
#pragma unroll
    for (int i = 0; i < K2; i++) wreg[i] = Wh[(K1 + i) * ZC + tid];

    for (int i = tid; i < G * LL; i += 512) {
        int g = i >> 8, t = i & 255;
        tok_s[g][t] = inputs[(b0 + g) * LL + t];
    }
    for (int i = tid; i < RNN * G; i += 512) ((float*)h_s)[i] = 0.0f;
    __syncthreads();

    int gate = tid >> 7, unit = tid & 127;
    float c0 = 0.0f, c1 = 0.0f;

    int t0 = dir ? (LL - 1) : 0;
    float pf[G];
#pragma unroll
    for (int g = 0; g < G; g++) pf[g] = g_P[dir][tok_s[g][t0]][tid];

    for (int step = 0; step < LL; step++) {
        int t = dir ? (LL - 1 - step) : step;

        u64 acc[G / 2];
#pragma unroll
        for (int p = 0; p < G / 2; p++) acc[p] = pk2(pf[2 * p], pf[2 * p + 1]);

        // prefetch next step's P rows (latency hidden behind the k loop)
        int tn = (step + 1 < LL) ? (dir ? t - 1 : t + 1) : t;
#pragma unroll
        for (int g = 0; g < G; g++) pf[g] = g_P[dir][tok_s[g][tn]][tid];

        const float* ws = Wh_s + tid;
#pragma unroll 8
        for (int k = 0; k < K1; k++) {
            float w = ws[k * ZC];
            u64 wd = pk2(w, w);
            ulonglong2 ha = *(const ulonglong2*)&h_s[k][0];   // LDS.128
            ulonglong2 hb = *(const ulonglong2*)&h_s[k][4];   // LDS.128
            ffma2(acc[0], wd, ha.x);
            ffma2(acc[1], wd, ha.y);
            ffma2(acc[2], wd, hb.x);
            ffma2(acc[3], wd, hb.y);
        }
#pragma unroll
        for (int i = 0; i < K2; i++) {
            u64 wd = pk2(wreg[i], wreg[i]);
            ulonglong2 ha = *(const ulonglong2*)&h_s[K1 + i][0];
            ulonglong2 hb = *(const ulonglong2*)&h_s[K1 + i][4];
            ffma2(acc[0], wd, ha.x);
            ffma2(acc[1], wd, ha.y);
            ffma2(acc[2], wd, hb.x);
            ffma2(acc[3], wd, hb.y);
        }

        // activations: gates 0,1,3 -> sigmoid; gate 2 -> tanh (MUFU fast paths)
#pragma unroll
        for (int p = 0; p < G / 2; p++) {
            float zlo, zhi; upk2(acc[p], zlo, zhi);
            float a0, a1;
            if (gate == 2) { a0 = fast_tanh(zlo); a1 = fast_tanh(zhi); }
            else           { a0 = fast_sigmoid(zlo); a1 = fast_sigmoid(zhi); }
            act_s[gate][2 * p][unit]     = a0;
            act_s[gate][2 * p + 1][unit] = a1;
        }
        __syncthreads();

        // c/h update: 1024 cells, 2 per thread; c lives in registers
        {
            int g = tid >> 7, u = tid & 127;
            float iv = act_s[0][g][u], fv = act_s[1][g][u];
            float gv = act_s[2][g][u], ov = act_s[3][g][u];
            c0 = fv * c0 + iv * gv;
            float h = ov * fast_tanh(c0);
            h_s[u][g] = h;
            g_hcat[t][b0 + g][dir * RNN + u] = h;

            int idx = tid + 512; int g2 = idx >> 7, u2 = idx & 127;
            float iv2 = act_s[0][g2][u2], fv2 = act_s[1][g2][u2];
            float gv2 = act_s[2][g2][u2], ov2 = act_s[3][g2][u2];
            c1 = fv2 * c1 + iv2 * gv2;
            float h2 = ov2 * fast_tanh(c1);
            h_s[u2][g2] = h2;
            g_hcat[t][b0 + g2][dir * RNN + u2] = h2;
        }
        __syncthreads();
    }
}

// ---------------------------------------------------------------------------
// Kernel 3: logits[b][t][k] = hcat[bt] . Wd[:,k] + bd[k]
// ---------------------------------------------------------------------------
__global__ __launch_bounds__(512) void logits_kernel(
    const float* __restrict__ Wd, const float* __restrict__ bd)
{
    __shared__ __align__(16) float h_s[LR][2 * RNN];
    __shared__ __align__(16) float2 Wt2[KK][RNN + 1];
    __shared__ float bd_s[KK];

    int tid = threadIdx.x;
    int bt0 = blockIdx.x * LR;

    for (int i = tid; i < KK * RNN; i += 512) {
        int k = i / RNN, e2 = i % RNN;
        Wt2[k][e2] = make_float2(Wd[(2 * e2) * KK + k], Wd[(2 * e2 + 1) * KK + k]);
    }
    if (tid < KK) bd_s[tid] = bd[tid];
    for (int i = tid; i < LR * 2 * RNN; i += 512) {
        int r = i >> 8, e = i & 255;
        int bt = bt0 + r;
        if (bt < BB * LL) {
            int b = bt >> 8, t = bt & 255;
            h_s[r][e] = g_hcat[t][b][e];
        }
    }
    __syncthreads();

    if (tid >= LR * KK) return;
    int r = tid / KK, k = tid % KK;
    int bt = bt0 + r;
    if (bt >= BB * LL) return;

    u64 acc = 0;
    const u64* hp = (const u64*)&h_s[r][0];
    const u64* wp = (const u64*)&Wt2[k][0];
#pragma unroll 8
    for (int e2 = 0; e2 < RNN; e2++) ffma2(acc, hp[e2], wp[e2]);

    float lo, hi; upk2(acc, lo, hi);
    int b = bt >> 8, t = bt & 255;
    g_logits[b][t][k] = lo + hi + bd_s[k];
}

// ---------------------------------------------------------------------------
// Kernel 4: CRF log-likelihood (+ fused T copy in the extra block).
// One warp per batch row; lanes 0..17 = classes. Fast-math exp/log.
// ---------------------------------------------------------------------------
__global__ __launch_bounds__(128) void crf_kernel(
    const int* __restrict__ labels, const float* __restrict__ T,
    float* __restrict__ out, int out_size)
{
    // extra block copies T (second output of the reference tuple)
    if (blockIdx.x == BB / 4) {
        for (int i = threadIdx.x; i < KK * KK; i += 128)
            if ((BB + i) < out_size) out[BB + i] = T[i];
        return;
    }

    __shared__ float T_s[KK * KK];
    int tid = threadIdx.x;
    for (int i = tid; i < KK * KK; i += 128) T_s[i] = T[i];
    __syncthreads();

    int warp = tid >> 5;
    int lane = tid & 31;
    int b = blockIdx.x * 4 + warp;
    if (b >= BB) return;

    const int* lab = labels + b * LL;

    int cnt = 0;
    for (int l = lane; l < LL; l += 32) cnt += (lab[l] != 0);
#pragma unroll
    for (int off = 16; off; off >>= 1) cnt += __shfl_xor_sync(0xffffffffu, cnt, off);
    int len = cnt;

    float us = 0.0f, bs = 0.0f;
    for (int l = lane; l < LL; l += 32) {
        int y = lab[l];
        if (l < len) us += g_logits[b][l][y];
        if (l >= 1 && l < len) bs += T_s[lab[l - 1] * KK + y];
    }
#pragma unroll
    for (int off = 16; off; off >>= 1) {
        us += __shfl_xor_sync(0xffffffffu, us, off);
        bs += __shfl_xor_sync(0xffffffffu, bs, off);
    }

    int k = (lane < KK) ? lane : 0;
    float alpha = (lane < KK) ? g_logits[b][0][k] : -1e30f;
    for (int l = 1; l < LL; l++) {
        float v[KK];
        float vmax = -1e30f;
#pragma unroll
        for (int k1 = 0; k1 < KK; k1++) {
            float ak = __shfl_sync(0xffffffffu, alpha, k1);
            v[k1] = ak + T_s[k1 * KK + k];
            vmax = fmaxf(vmax, v[k1]);
        }
        float s = 0.0f;
#pragma unroll
        for (int k1 = 0; k1 < KK; k1++) s += __expf(v[k1] - vmax);
        float na = vmax + __logf(s) + g_logits[b][l][k];
        if (lane < KK && l < len) alpha = na;
    }

    float m = alpha;
#pragma unroll
    for (int off = 16; off; off >>= 1) m = fmaxf(m, __shfl_xor_sync(0xffffffffu, m, off));
    float es = (lane < KK) ? __expf(alpha - m) : 0.0f;
#pragma unroll
    for (int off = 16; off; off >>= 1) es += __shfl_xor_sync(0xffffffffu, es, off);
    float lse = m + __logf(es);

    if (lane == 0 && b < out_size) out[b] = us + bs - lse;
}

// ---------------------------------------------------------------------------
extern "C" void kernel_launch(void* const* d_in, const int* in_sizes, int n_in,
                              void* d_out, int out_size)
{
    const int*   inputs = (const int*)  d_in[0];
    const int*   labels = (const int*)  d_in[1];
    const float* E      = (const float*)d_in[2];
    const float* Wx_f   = (const float*)d_in[3];
    const float* Wh_f   = (const float*)d_in[4];
    const float* b_f    = (const float*)d_in[5];
    const float* Wx_b   = (const float*)d_in[6];
    const float* Wh_b   = (const float*)d_in[7];
    const float* b_b    = (const float*)d_in[8];
    const float* Wd     = (const float*)d_in[9];
    const float* bd     = (const float*)d_in[10];
    const float* T      = (const float*)d_in[11];
    float* out = (float*)d_out;

    const int lstm_smem = K1 * ZC * 4 + RNN * G * 4 + 4 * G * RNN * 4 + G * LL * 4;
    cudaFuncSetAttribute(lstm_kernel, cudaFuncAttributeMaxDynamicSharedMemorySize, lstm_smem);

    dim3 pg((VOCAB + PG - 1) / PG, 2);
    pbuild_kernel<<<pg, 512>>>(E, Wx_f, b_f, Wx_b, b_b);
    lstm_kernel<<<128, 512, lstm_smem>>>(inputs, Wh_f, Wh_b);
    int nbt = BB * LL;
    logits_kernel<<<(nbt + LR - 1) / LR, 512>>>(Wd, bd);
    crf_kernel<<<BB / 4 + 1, 128>>>(labels, T, out, out_size);
}

// round 5
// speedup vs baseline: 1.7197x; 1.0032x over previous
#include <cuda_runtime.h>
#include <math.h>

#define EMB 64
#define RNN 128
#define BB  512
#define LL  256
#define KK  18
#define G   8
#define ZC  512   // 4*RNN
#define VOCAB 30001
#define K1  80    // Wh rows cached in smem
#define K2  48    // Wh rows cached in registers (RNN - K1)
#define PG  32    // vocab rows per pbuild block
#define LR  28    // (b,t) rows per logits block

// Scratch (static device allocations; no cudaMalloc allowed)
__device__ float g_P[2][VOCAB][ZC];        // E@Wx + b per dir (~123 MB)
__device__ float g_hcat[LL][BB][2 * RNN];  // concat(h_fwd, h_bwd)
__device__ float g_logits[BB][LL][KK];

typedef unsigned long long u64;

__device__ __forceinline__ u64 pk2(float lo, float hi) {
    u64 r; asm("mov.b64 %0,{%1,%2};" : "=l"(r) : "f"(lo), "f"(hi)); return r;
}
__device__ __forceinline__ void upk2(u64 v, float& lo, float& hi) {
    asm("mov.b64 {%0,%1},%2;" : "=f"(lo), "=f"(hi) : "l"(v));
}
__device__ __forceinline__ void ffma2(u64& d, u64 a, u64 b) {
    asm("fma.rn.f32x2 %0,%1,%2,%0;" : "+l"(d) : "l"(a), "l"(b));
}
__device__ __forceinline__ float fast_tanh(float x) {
    float y; asm("tanh.approx.f32 %0, %1;" : "=f"(y) : "f"(x)); return y;
}
__device__ __forceinline__ float fast_sigmoid(float x) {
    return __fdividef(1.0f, 1.0f + __expf(-x));
}

// ---------------------------------------------------------------------------
// Kernel 1: P[dir][v][:] = E[v] @ Wx_dir + b_dir  (vocab-level factoring)
// ---------------------------------------------------------------------------
__global__ __launch_bounds__(512) void pbuild_kernel(
    const float* __restrict__ E,
    const float* __restrict__ Wx_f, const float* __restrict__ b_f,
    const float* __restrict__ Wx_b, const float* __restrict__ b_b)
{
    int dir = blockIdx.y;
    int r0  = blockIdx.x * PG;
    const float* __restrict__ Wx = dir ? Wx_b : Wx_f;
    const float* __restrict__ bs = dir ? b_b : b_f;

    __shared__ __align__(16) float x_s[EMB][PG];
    int tid = threadIdx.x;
    for (int i = tid; i < PG * EMB; i += 512) {
        int r = i >> 6, e = i & 63;
        int row = r0 + r;
        x_s[e][r] = (row < VOCAB) ? E[row * EMB + e] : 0.0f;
    }
    __syncthreads();

    float bv = bs[tid];
    u64 bp = pk2(bv, bv);
    u64 acc[PG / 2];
#pragma unroll
    for (int p = 0; p < PG / 2; p++) acc[p] = bp;

    const float* wc = Wx + tid;
#pragma unroll 4
    for (int e = 0; e < EMB; e++) {
        float w = wc[e * ZC];
        u64 wd = pk2(w, w);
        const u64* xp = (const u64*)&x_s[e][0];
#pragma unroll
        for (int p = 0; p < PG / 2; p++) ffma2(acc[p], wd, xp[p]);
    }

#pragma unroll
    for (int p = 0; p < PG / 2; p++) {
        float lo, hi; upk2(acc[p], lo, hi);
        int ra = r0 + 2 * p, rb = ra + 1;
        if (ra < VOCAB) g_P[dir][ra][tid] = lo;
        if (rb < VOCAB) g_P[dir][rb][tid] = hi;
    }
}

// ---------------------------------------------------------------------------
// Kernel 2: persistent LSTM. 128 blocks = 2 dirs x 64 batch-groups (G=8 rows).
// Wh on-chip: 80 rows smem + 48 rows regs. h loads as LDS.128. MUFU activations.
// ---------------------------------------------------------------------------
__global__ __launch_bounds__(512, 1) void lstm_kernel(
    const int* __restrict__ inputs,
    const float* __restrict__ Wh_f, const float* __restrict__ Wh_b)
{
    extern __shared__ char lsm[];
    float* Wh_s = (float*)lsm;                                                          // K1*ZC
    float (*h_s)[G]        = (float(*)[G])      (lsm + K1 * ZC * 4);                    // [RNN][G]
    float (*act_s)[G][RNN] = (float(*)[G][RNN]) (lsm + K1 * ZC * 4 + RNN * G * 4);      // [4][G][RNN]
    int   (*tok_s)[LL]     = (int(*)[LL])       (lsm + K1 * ZC * 4 + RNN * G * 4 + 4 * G * RNN * 4);

    int dir = blockIdx.x >> 6;
    int bi  = blockIdx.x & 63;
    int b0  = bi * G;
    const float* __restrict__ Wh = dir ? Wh_b : Wh_f;
    int tid = threadIdx.x;

    for (int i = tid; i < K1 * ZC; i += 512) Wh_s[i] = Wh[i];
    float wreg[K2];
#pragma unroll
    for (int i = 0; i < K2; i++) wreg[i] = Wh[(K1 + i) * ZC + tid];

    for (int i = tid; i < G * LL; i += 512) {
        int g = i >> 8, t = i & 255;
        tok_s[g][t] = inputs[(b0 + g) * LL + t];
    }
    for (int i = tid; i < RNN * G; i += 512) ((float*)h_s)[i] = 0.0f;
    __syncthreads();

    int gate = tid >> 7, unit = tid & 127;
    float c0 = 0.0f, c1 = 0.0f;

    int t0 = dir ? (LL - 1) : 0;
    float pf[G];
#pragma unroll
    for (int g = 0; g < G; g++) pf[g] = g_P[dir][tok_s[g][t0]][tid];

    for (int step = 0; step < LL; step++) {
        int t = dir ? (LL - 1 - step) : step;

        u64 acc[G / 2];
#pragma unroll
        for (int p = 0; p < G / 2; p++) acc[p] = pk2(pf[2 * p], pf[2 * p + 1]);

        // prefetch next step's P rows (latency hidden behind the k loop)
        int tn = (step + 1 < LL) ? (dir ? t - 1 : t + 1) : t;
#pragma unroll
        for (int g = 0; g < G; g++) pf[g] = g_P[dir][tok_s[g][tn]][tid];

        const float* ws = Wh_s + tid;
#pragma unroll 8
        for (int k = 0; k < K1; k++) {
            float w = ws[k * ZC];
            u64 wd = pk2(w, w);
            ulonglong2 ha = *(const ulonglong2*)&h_s[k][0];   // LDS.128
            ulonglong2 hb = *(const ulonglong2*)&h_s[k][4];   // LDS.128
            ffma2(acc[0], wd, ha.x);
            ffma2(acc[1], wd, ha.y);
            ffma2(acc[2], wd, hb.x);
            ffma2(acc[3], wd, hb.y);
        }
#pragma unroll
        for (int i = 0; i < K2; i++) {
            u64 wd = pk2(wreg[i], wreg[i]);
            ulonglong2 ha = *(const ulonglong2*)&h_s[K1 + i][0];
            ulonglong2 hb = *(const ulonglong2*)&h_s[K1 + i][4];
            ffma2(acc[0], wd, ha.x);
            ffma2(acc[1], wd, ha.y);
            ffma2(acc[2], wd, hb.x);
            ffma2(acc[3], wd, hb.y);
        }

        // activations: gates 0,1,3 -> sigmoid; gate 2 -> tanh (MUFU fast paths)
#pragma unroll
        for (int p = 0; p < G / 2; p++) {
            float zlo, zhi; upk2(acc[p], zlo, zhi);
            float a0, a1;
            if (gate == 2) { a0 = fast_tanh(zlo); a1 = fast_tanh(zhi); }
            else           { a0 = fast_sigmoid(zlo); a1 = fast_sigmoid(zhi); }
            act_s[gate][2 * p][unit]     = a0;
            act_s[gate][2 * p + 1][unit] = a1;
        }
        __syncthreads();

        // c/h update: 1024 cells, 2 per thread; c lives in registers
        {
            int g = tid >> 7, u = tid & 127;
            float iv = act_s[0][g][u], fv = act_s[1][g][u];
            float gv = act_s[2][g][u], ov = act_s[3][g][u];
            c0 = fv * c0 + iv * gv;
            float h = ov * fast_tanh(c0);
            h_s[u][g] = h;
            g_hcat[t][b0 + g][dir * RNN + u] = h;

            int idx = tid + 512; int g2 = idx >> 7, u2 = idx & 127;
            float iv2 = act_s[0][g2][u2], fv2 = act_s[1][g2][u2];
            float gv2 = act_s[2][g2][u2], ov2 = act_s[3][g2][u2];
            c1 = fv2 * c1 + iv2 * gv2;
            float h2 = ov2 * fast_tanh(c1);
            h_s[u2][g2] = h2;
            g_hcat[t][b0 + g2][dir * RNN + u2] = h2;
        }
        __syncthreads();
    }
}

// ---------------------------------------------------------------------------
// Kernel 3: logits[b][t][k] = hcat[bt] . Wd[:,k] + bd[k]
// ---------------------------------------------------------------------------
__global__ __launch_bounds__(512) void logits_kernel(
    const float* __restrict__ Wd, const float* __restrict__ bd)
{
    __shared__ __align__(16) float h_s[LR][2 * RNN];
    __shared__ __align__(16) float2 Wt2[KK][RNN + 1];
    __shared__ float bd_s[KK];

    int tid = threadIdx.x;
    int bt0 = blockIdx.x * LR;

    for (int i = tid; i < KK * RNN; i += 512) {
        int k = i / RNN, e2 = i % RNN;
        Wt2[k][e2] = make_float2(Wd[(2 * e2) * KK + k], Wd[(2 * e2 + 1) * KK + k]);
    }
    if (tid < KK) bd_s[tid] = bd[tid];
    for (int i = tid; i < LR * 2 * RNN; i += 512) {
        int r = i >> 8, e = i & 255;
        int bt = bt0 + r;
        if (bt < BB * LL) {
            int b = bt >> 8, t = bt & 255;
            h_s[r][e] = g_hcat[t][b][e];
        }
    }
    __syncthreads();

    if (tid >= LR * KK) return;
    int r = tid / KK, k = tid % KK;
    int bt = bt0 + r;
    if (bt >= BB * LL) return;

    u64 acc = 0;
    const u64* hp = (const u64*)&h_s[r][0];
    const u64* wp = (const u64*)&Wt2[k][0];
#pragma unroll 8
    for (int e2 = 0; e2 < RNN; e2++) ffma2(acc, hp[e2], wp[e2]);

    float lo, hi; upk2(acc, lo, hi);
    int b = bt >> 8, t = bt & 255;
    g_logits[b][t][k] = lo + hi + bd_s[k];
}

// ---------------------------------------------------------------------------
// Kernel 4: CRF log-likelihood (+ fused T copy in the extra block).
// One warp per batch row; lanes 0..17 = classes. Fast-math exp/log.
// ---------------------------------------------------------------------------
__global__ __launch_bounds__(128) void crf_kernel(
    const int* __restrict__ labels, const float* __restrict__ T,
    float* __restrict__ out, int out_size)
{
    // extra block copies T (second output of the reference tuple)
    if (blockIdx.x == BB / 4) {
        for (int i = threadIdx.x; i < KK * KK; i += 128)
            if ((BB + i) < out_size) out[BB + i] = T[i];
        return;
    }

    __shared__ float T_s[KK * KK];
    int tid = threadIdx.x;
    for (int i = tid; i < KK * KK; i += 128) T_s[i] = T[i];
    __syncthreads();

    int warp = tid >> 5;
    int lane = tid & 31;
    int b = blockIdx.x * 4 + warp;
    if (b >= BB) return;

    const int* lab = labels + b * LL;

    int cnt = 0;
    for (int l = lane; l < LL; l += 32) cnt += (lab[l] != 0);
#pragma unroll
    for (int off = 16; off; off >>= 1) cnt += __shfl_xor_sync(0xffffffffu, cnt, off);
    int len = cnt;

    float us = 0.0f, bs = 0.0f;
    for (int l = lane; l < LL; l += 32) {
        int y = lab[l];
        if (l < len) us += g_logits[b][l][y];
        if (l >= 1 && l < len) bs += T_s[lab[l - 1] * KK + y];
    }
#pragma unroll
    for (int off = 16; off; off >>= 1) {
        us += __shfl_xor_sync(0xffffffffu, us, off);
        bs += __shfl_xor_sync(0xffffffffu, bs, off);
    }

    int k = (lane < KK) ? lane : 0;
    float alpha = (lane < KK) ? g_logits[b][0][k] : -1e30f;
    for (int l = 1; l < LL; l++) {
        float v[KK];
        float vmax = -1e30f;
#pragma unroll
        for (int k1 = 0; k1 < KK; k1++) {
            float ak = __shfl_sync(0xffffffffu, alpha, k1);
            v[k1] = ak + T_s[k1 * KK + k];
            vmax = fmaxf(vmax, v[k1]);
        }
        float s = 0.0f;
#pragma unroll
        for (int k1 = 0; k1 < KK; k1++) s += __expf(v[k1] - vmax);
        float na = vmax + __logf(s) + g_logits[b][l][k];
        if (lane < KK && l < len) alpha = na;
    }

    float m = alpha;
#pragma unroll
    for (int off = 16; off; off >>= 1) m = fmaxf(m, __shfl_xor_sync(0xffffffffu, m, off));
    float es = (lane < KK) ? __expf(alpha - m) : 0.0f;
#pragma unroll
    for (int off = 16; off; off >>= 1) es += __shfl_xor_sync(0xffffffffu, es, off);
    float lse = m + __logf(es);

    if (lane == 0 && b < out_size) out[b] = us + bs - lse;
}

// ---------------------------------------------------------------------------
extern "C" void kernel_launch(void* const* d_in, const int* in_sizes, int n_in,
                              void* d_out, int out_size)
{
    const int*   inputs = (const int*)  d_in[0];
    const int*   labels = (const int*)  d_in[1];
    const float* E      = (const float*)d_in[2];
    const float* Wx_f   = (const float*)d_in[3];
    const float* Wh_f   = (const float*)d_in[4];
    const float* b_f    = (const float*)d_in[5];
    const float* Wx_b   = (const float*)d_in[6];
    const float* Wh_b   = (const float*)d_in[7];
    const float* b_b    = (const float*)d_in[8];
    const float* Wd     = (const float*)d_in[9];
    const float* bd     = (const float*)d_in[10];
    const float* T      = (const float*)d_in[11];
    float* out = (float*)d_out;

    const int lstm_smem = K1 * ZC * 4 + RNN * G * 4 + 4 * G * RNN * 4 + G * LL * 4;
    cudaFuncSetAttribute(lstm_kernel, cudaFuncAttributeMaxDynamicSharedMemorySize, lstm_smem);

    dim3 pg((VOCAB + PG - 1) / PG, 2);
    pbuild_kernel<<<pg, 512>>>(E, Wx_f, b_f, Wx_b, b_b);
    lstm_kernel<<<128, 512, lstm_smem>>>(inputs, Wh_f, Wh_b);
    int nbt = BB * LL;
    logits_kernel<<<(nbt + LR - 1) / LR, 512>>>(Wd, bd);
    crf_kernel<<<BB / 4 + 1, 128>>>(labels, T, out, out_size);
}

// round 6
// speedup vs baseline: 4.1194x; 2.3954x over previous
#include <cuda_runtime.h>
#include <cuda_bf16.h>
#include <math.h>

#define EMB 64
#define RNN 128
#define BB  512
#define LL  256
#define KK  18
#define G   8
#define ZC  512   // 4*RNN
#define VOCAB 30001
#define PG  32    // vocab rows per pbuild block
#define LR  28    // (b,t) rows per logits block
#define ZPAD 520  // padded z row (floats)

// Scratch (static device allocations; no cudaMalloc allowed)
__device__ float g_P[2][VOCAB][ZC];        // E@Wx + b per dir (~123 MB)
__device__ float g_hcat[LL][BB][2 * RNN];  // concat(h_fwd, h_bwd)
__device__ float g_logits[BB][LL][KK];

typedef unsigned long long u64;
typedef unsigned int u32;

__device__ __forceinline__ u64 pk2(float lo, float hi) {
    u64 r; asm("mov.b64 %0,{%1,%2};" : "=l"(r) : "f"(lo), "f"(hi)); return r;
}
__device__ __forceinline__ void upk2(u64 v, float& lo, float& hi) {
    asm("mov.b64 {%0,%1},%2;" : "=f"(lo), "=f"(hi) : "l"(v));
}
__device__ __forceinline__ void ffma2(u64& d, u64 a, u64 b) {
    asm("fma.rn.f32x2 %0,%1,%2,%0;" : "+l"(d) : "l"(a), "l"(b));
}
__device__ __forceinline__ float fast_tanh(float x) {
    float y; asm("tanh.approx.f32 %0, %1;" : "=f"(y) : "f"(x)); return y;
}
__device__ __forceinline__ float fast_sig(float x) {
    return 0.5f * fast_tanh(0.5f * x) + 0.5f;
}
__device__ __forceinline__ u32 pack_bf16(float lo, float hi) {
    __nv_bfloat162 v = __floats2bfloat162_rn(lo, hi);  // .x = lo (low 16 bits)
    return *(u32*)&v;
}
__device__ __forceinline__ void mma16816(float& d0, float& d1, float& d2, float& d3,
                                         u32 a0, u32 a1, u32 a2, u32 a3,
                                         u32 b0, u32 b1) {
    asm("mma.sync.aligned.m16n8k16.row.col.f32.bf16.bf16.f32 "
        "{%0,%1,%2,%3}, {%4,%5,%6,%7}, {%8,%9}, {%0,%1,%2,%3};"
        : "+f"(d0), "+f"(d1), "+f"(d2), "+f"(d3)
        : "r"(a0), "r"(a1), "r"(a2), "r"(a3), "r"(b0), "r"(b1));
}

// ---------------------------------------------------------------------------
// Kernel 1: P[dir][v][:] = E[v] @ Wx_dir + b_dir  (vocab-level factoring)
// ---------------------------------------------------------------------------
__global__ __launch_bounds__(512) void pbuild_kernel(
    const float* __restrict__ E,
    const float* __restrict__ Wx_f, const float* __restrict__ b_f,
    const float* __restrict__ Wx_b, const float* __restrict__ b_b)
{
    int dir = blockIdx.y;
    int r0  = blockIdx.x * PG;
    const float* __restrict__ Wx = dir ? Wx_b : Wx_f;
    const float* __restrict__ bs = dir ? b_b : b_f;

    __shared__ __align__(16) float x_s[EMB][PG];
    int tid = threadIdx.x;
    for (int i = tid; i < PG * EMB; i += 512) {
        int r = i >> 6, e = i & 63;
        int row = r0 + r;
        x_s[e][r] = (row < VOCAB) ? E[row * EMB + e] : 0.0f;
    }
    __syncthreads();

    float bv = bs[tid];
    u64 bp = pk2(bv, bv);
    u64 acc[PG / 2];
#pragma unroll
    for (int p = 0; p < PG / 2; p++) acc[p] = bp;

    const float* wc = Wx + tid;
#pragma unroll 4
    for (int e = 0; e < EMB; e++) {
        float w = wc[e * ZC];
        u64 wd = pk2(w, w);
        const u64* xp = (const u64*)&x_s[e][0];
#pragma unroll
        for (int p = 0; p < PG / 2; p++) ffma2(acc[p], wd, xp[p]);
    }

#pragma unroll
    for (int p = 0; p < PG / 2; p++) {
        float lo, hi; upk2(acc[p], lo, hi);
        int ra = r0 + 2 * p, rb = ra + 1;
        if (ra < VOCAB) g_P[dir][ra][tid] = lo;
        if (rb < VOCAB) g_P[dir][rb][tid] = hi;
    }
}

// ---------------------------------------------------------------------------
// Kernel 2: persistent LSTM via mma.sync m16n8k16 bf16 (fp32 accumulate).
// 128 blocks = 2 dirs x 64 batch-groups (G=8 rows, padded to M=16).
// Wh bf16 B-fragments live in registers; h in fragment-ready smem layout.
// ---------------------------------------------------------------------------
__global__ __launch_bounds__(512, 1) void lstm_kernel(
    const int* __restrict__ inputs,
    const float* __restrict__ Wh_f, const float* __restrict__ Wh_b)
{
    __shared__ __align__(16) u32 hfrag[8 * 128];      // 8 chunks x 32 lanes x 16B = 4KB
    __shared__ float z_s[G][ZPAD];                    // z exchange, padded rows
    __shared__ int tok_s[G][LL];

    int dir = blockIdx.x >> 6;
    int bi  = blockIdx.x & 63;
    int b0  = bi * G;
    const float* __restrict__ Wh = dir ? Wh_b : Wh_f;
    int tid  = threadIdx.x;
    int w    = tid >> 5;       // warp 0..15: owns n-cols [32w, 32w+32)
    int lane = tid & 31;
    int gm   = lane >> 2;      // 0..7 = batch row within group (A row)
    int tl   = lane & 3;       // 0..3 = k/col pair selector

    // init: zero h fragments (incl. pad rows a1/a3 slots, never written again)
    for (int i = tid; i < 8 * 128; i += 512) hfrag[i] = 0u;
    // tokens
    for (int i = tid; i < G * LL; i += 512) {
        int g = i >> 8, t = i & 255;
        tok_s[g][t] = inputs[(b0 + g) * LL + t];
    }

    // Wh -> bf16 B fragments in registers: bfrag[nt][kc][0..1]
    // b0 = {Wh[kb][n], Wh[kb+1][n]}, b1 = {Wh[kb+8][n], Wh[kb+9][n]},
    // kb = 16*kc + 2*tl, n = 32w + 8nt + gm
    u32 bfr[4][8][2];
#pragma unroll
    for (int nt = 0; nt < 4; nt++) {
        int n = w * 32 + nt * 8 + gm;
#pragma unroll
        for (int kc = 0; kc < 8; kc++) {
            int kb = 16 * kc + 2 * tl;
            bfr[nt][kc][0] = pack_bf16(Wh[kb * ZC + n],       Wh[(kb + 1) * ZC + n]);
            bfr[nt][kc][1] = pack_bf16(Wh[(kb + 8) * ZC + n], Wh[(kb + 9) * ZC + n]);
        }
    }
    __syncthreads();

    // update-phase thread mapping: cell rows g, unit pair (2j, 2j+1)
    int ug = tid >> 6;         // 0..7
    int uj = tid & 63;         // 0..63
    int u0 = 2 * uj;
    int ucc = u0 & 15;
    int ukc = u0 >> 4;
    // h-fragment write slot for (ug, u0): byte addr = ukc*512 + (ug*4+t)*16 + (cc&8)
    int hw_idx = (ukc * 512 + ((ug << 2) | ((ucc >> 1) & 3)) * 16 + (ucc & 8)) >> 2;
    float c0 = 0.0f, c1 = 0.0f;

    // P prefetch (fp32 acc init), one step ahead
    int t0 = dir ? (LL - 1) : 0;
    float2 pf[4];
#pragma unroll
    for (int nt = 0; nt < 4; nt++)
        pf[nt] = *(const float2*)&g_P[dir][tok_s[gm][t0]][w * 32 + nt * 8 + 2 * tl];

    for (int step = 0; step < LL; step++) {
        int t = dir ? (LL - 1 - step) : step;

        // acc init from P (rows 8-15 are padding, stay 0)
        float d0[4], d1[4], d2[4], d3[4];
#pragma unroll
        for (int nt = 0; nt < 4; nt++) {
            d0[nt] = pf[nt].x; d1[nt] = pf[nt].y; d2[nt] = 0.0f; d3[nt] = 0.0f;
        }

        // prefetch next step's P rows (hidden behind MMA loop)
        int tn = (step + 1 < LL) ? (dir ? t - 1 : t + 1) : t;
#pragma unroll
        for (int nt = 0; nt < 4; nt++)
            pf[nt] = *(const float2*)&g_P[dir][tok_s[gm][tn]][w * 32 + nt * 8 + 2 * tl];

        // MMA mainloop over K chunks
#pragma unroll
        for (int kc = 0; kc < 8; kc++) {
            uint4 af = *(const uint4*)&hfrag[(kc * 512 + lane * 16) >> 2];
#pragma unroll
            for (int nt = 0; nt < 4; nt++)
                mma16816(d0[nt], d1[nt], d2[nt], d3[nt],
                         af.x, af.y, af.z, af.w,
                         bfr[nt][kc][0], bfr[nt][kc][1]);
        }

        // store z (valid rows only: d0/d1 cover rows 0-7)
#pragma unroll
        for (int nt = 0; nt < 4; nt++) {
            *(float2*)&z_s[gm][w * 32 + nt * 8 + 2 * tl] = make_float2(d0[nt], d1[nt]);
        }
        __syncthreads();

        // gate -> c,h update: thread handles cells (ug, u0), (ug, u0+1)
        {
            float2 iv = *(const float2*)&z_s[ug][0 * RNN + u0];
            float2 fv = *(const float2*)&z_s[ug][1 * RNN + u0];
            float2 gv = *(const float2*)&z_s[ug][2 * RNN + u0];
            float2 ov = *(const float2*)&z_s[ug][3 * RNN + u0];
            c0 = fast_sig(fv.x) * c0 + fast_sig(iv.x) * fast_tanh(gv.x);
            c1 = fast_sig(fv.y) * c1 + fast_sig(iv.y) * fast_tanh(gv.y);
            float h0 = fast_sig(ov.x) * fast_tanh(c0);
            float h1 = fast_sig(ov.y) * fast_tanh(c1);
            hfrag[hw_idx] = pack_bf16(h0, h1);
            *(float2*)&g_hcat[t][b0 + ug][dir * RNN + u0] = make_float2(h0, h1);
        }
        __syncthreads();
    }
}

// ---------------------------------------------------------------------------
// Kernel 3: logits[b][t][k] = hcat[bt] . Wd[:,k] + bd[k]
// ---------------------------------------------------------------------------
__global__ __launch_bounds__(512) void logits_kernel(
    const float* __restrict__ Wd, const float* __restrict__ bd)
{
    __shared__ __align__(16) float h_s[LR][2 * RNN];
    __shared__ __align__(16) float2 Wt2[KK][RNN + 1];
    __shared__ float bd_s[KK];

    int tid = threadIdx.x;
    int bt0 = blockIdx.x * LR;

    for (int i = tid; i < KK * RNN; i += 512) {
        int k = i / RNN, e2 = i % RNN;
        Wt2[k][e2] = make_float2(Wd[(2 * e2) * KK + k], Wd[(2 * e2 + 1) * KK + k]);
    }
    if (tid < KK) bd_s[tid] = bd[tid];
    for (int i = tid; i < LR * 2 * RNN; i += 512) {
        int r = i >> 8, e = i & 255;
        int bt = bt0 + r;
        if (bt < BB * LL) {
            int b = bt >> 8, t = bt & 255;
            h_s[r][e] = g_hcat[t][b][e];
        }
    }
    __syncthreads();

    if (tid >= LR * KK) return;
    int r = tid / KK, k = tid % KK;
    int bt = bt0 + r;
    if (bt >= BB * LL) return;

    u64 acc = 0;
    const u64* hp = (const u64*)&h_s[r][0];
    const u64* wp = (const u64*)&Wt2[k][0];
#pragma unroll 8
    for (int e2 = 0; e2 < RNN; e2++) ffma2(acc, hp[e2], wp[e2]);

    float lo, hi; upk2(acc, lo, hi);
    int b = bt >> 8, t = bt & 255;
    g_logits[b][t][k] = lo + hi + bd_s[k];
}

// ---------------------------------------------------------------------------
// Kernel 4: CRF log-likelihood (+ fused T copy in the extra block).
// ---------------------------------------------------------------------------
__global__ __launch_bounds__(128) void crf_kernel(
    const int* __restrict__ labels, const float* __restrict__ T,
    float* __restrict__ out, int out_size)
{
    if (blockIdx.x == BB / 4) {
        for (int i = threadIdx.x; i < KK * KK; i += 128)
            if ((BB + i) < out_size) out[BB + i] = T[i];
        return;
    }

    __shared__ float T_s[KK * KK];
    int tid = threadIdx.x;
    for (int i = tid; i < KK * KK; i += 128) T_s[i] = T[i];
    __syncthreads();

    int warp = tid >> 5;
    int lane = tid & 31;
    int b = blockIdx.x * 4 + warp;
    if (b >= BB) return;

    const int* lab = labels + b * LL;

    int cnt = 0;
    for (int l = lane; l < LL; l += 32) cnt += (lab[l] != 0);
#pragma unroll
    for (int off = 16; off; off >>= 1) cnt += __shfl_xor_sync(0xffffffffu, cnt, off);
    int len = cnt;

    float us = 0.0f, bs = 0.0f;
    for (int l = lane; l < LL; l += 32) {
        int y = lab[l];
        if (l < len) us += g_logits[b][l][y];
        if (l >= 1 && l < len) bs += T_s[lab[l - 1] * KK + y];
    }
#pragma unroll
    for (int off = 16; off; off >>= 1) {
        us += __shfl_xor_sync(0xffffffffu, us, off);
        bs += __shfl_xor_sync(0xffffffffu, bs, off);
    }

    int k = (lane < KK) ? lane : 0;
    float alpha = (lane < KK) ? g_logits[b][0][k] : -1e30f;
    for (int l = 1; l < LL; l++) {
        float v[KK];
        float vmax = -1e30f;
#pragma unroll
        for (int k1 = 0; k1 < KK; k1++) {
            float ak = __shfl_sync(0xffffffffu, alpha, k1);
            v[k1] = ak + T_s[k1 * KK + k];
            vmax = fmaxf(vmax, v[k1]);
        }
        float s = 0.0f;
#pragma unroll
        for (int k1 = 0; k1 < KK; k1++) s += __expf(v[k1] - vmax);
        float na = vmax + __logf(s) + g_logits[b][l][k];
        if (lane < KK && l < len) alpha = na;
    }

    float m = alpha;
#pragma unroll
    for (int off = 16; off; off >>= 1) m = fmaxf(m, __shfl_xor_sync(0xffffffffu, m, off));
    float es = (lane < KK) ? __expf(alpha - m) : 0.0f;
#pragma unroll
    for (int off = 16; off; off >>= 1) es += __shfl_xor_sync(0xffffffffu, es, off);
    float lse = m + __logf(es);

    if (lane == 0 && b < out_size) out[b] = us + bs - lse;
}

// ---------------------------------------------------------------------------
extern "C" void kernel_launch(void* const* d_in, const int* in_sizes, int n_in,
                              void* d_out, int out_size)
{
    const int*   inputs = (const int*)  d_in[0];
    const int*   labels = (const int*)  d_in[1];
    const float* E      = (const float*)d_in[2];
    const float* Wx_f   = (const float*)d_in[3];
    const float* Wh_f   = (const float*)d_in[4];
    const float* b_f    = (const float*)d_in[5];
    const float* Wx_b   = (const float*)d_in[6];
    const float* Wh_b   = (const float*)d_in[7];
    const float* b_b    = (const float*)d_in[8];
    const float* Wd     = (const float*)d_in[9];
    const float* bd     = (const float*)d_in[10];
    const float* T      = (const float*)d_in[11];
    float* out = (float*)d_out;

    dim3 pg((VOCAB + PG - 1) / PG, 2);
    pbuild_kernel<<<pg, 512>>>(E, Wx_f, b_f, Wx_b, b_b);
    lstm_kernel<<<128, 512>>>(inputs, Wh_f, Wh_b);
    int nbt = BB * LL;
    logits_kernel<<<(nbt + LR - 1) / LR, 512>>>(Wd, bd);
    crf_kernel<<<BB / 4 + 1, 128>>>(labels, T, out, out_size);
}